// round 6
// baseline (speedup 1.0000x reference)
#include <cuda_runtime.h>

// Fixed problem shape
#define BB 4
#define CC 19
#define HH 256
#define WW 256
#define HW (HH * WW)
#define CHW (CC * HW)
#define RAD 10
#define TS 32
#define EW (TS + 2 * RAD)   // 52 halo rows
#define NBLK2 256           // K2 block count (64 tiles x 4 images)

// Scratch (device globals; self-resetting at end of each replay)
__device__ float g_ent[BB * HW];
__device__ float g_kl[BB * HW];
__device__ unsigned char g_fg[BB * HW];
__device__ int g_entmax[BB];        // entropy > 0 -> int atomicMax is order-preserving
__device__ double g_sum_wkl;
__device__ double g_sum_w;
__device__ unsigned int g_done;     // K2 completion counter

// ---------------------------------------------------------------------------
// K1: 1 pixel/thread, max occupancy, perfectly coalesced. (at LTS roofline)
// ---------------------------------------------------------------------------
__global__ void __launch_bounds__(256) k1_channelwise(
    const float* __restrict__ student, const float* __restrict__ teacher)
{
    const int b = blockIdx.y;
    const int p = blockIdx.x * 256 + threadIdx.x;
    const size_t base = (size_t)b * CHW + p;

    float Z = 0.f, S = 0.f, Tt = 0.f, Zs = 0.f;
    float t0, mx = -1e30f;

#pragma unroll
    for (int c = 0; c < CC; c++) {
        float tv = __ldg(teacher + base + (size_t)c * HW) * 0.25f;
        float sv = __ldg(student + base + (size_t)c * HW) * 0.25f;
        float e = __expf(tv);
        Z += e;
        S = fmaf(e, tv, S);
        Tt = fmaf(e, sv, Tt);
        Zs += __expf(sv);
        if (c == 0) t0 = tv;
        else        mx = fmaxf(mx, tv);
    }

    const float lZ = __logf(Z);
    const float ent = lZ - S / Z;
    const float kl = (S - Tt) / Z - lZ + __logf(Zs);

    const int idx = b * HW + p;
    g_ent[idx] = ent;
    g_kl[idx] = kl;
    g_fg[idx] = (mx > t0) ? 1 : 0;   // argmax != 0 (ties -> class 0)

    float entm = ent;
#pragma unroll
    for (int o = 16; o > 0; o >>= 1)
        entm = fmaxf(entm, __shfl_xor_sync(0xFFFFFFFF, entm, o));
    __shared__ float smax[8];
    if ((threadIdx.x & 31) == 0) smax[threadIdx.x >> 5] = entm;
    __syncthreads();
    if (threadIdx.x == 0) {
        float m = smax[0];
#pragma unroll
        for (int w = 1; w < 8; w++) m = fmaxf(m, smax[w]);
        atomicMax(&g_entmax[b], __float_as_int(m));
    }
}

// ---------------------------------------------------------------------------
// K2: bounded EDT + weights + finalize. 1024 threads/block, 1 pixel/thread:
// 4x the warps of the previous version (55 warps/SM) to hide L2/LDS latency.
// Each thread computes the byte-SIMD 21-tap horizontal min for its aligned
// 4-pixel group (redundant across 4 threads) and extracts its own byte.
// ---------------------------------------------------------------------------
__global__ void __launch_bounds__(1024) k2_edt_weights(float* __restrict__ out)
{
    const int b  = blockIdx.y;
    const int i0 = (blockIdx.x >> 3) * TS;
    const int j0 = (blockIdx.x & 7) * TS;
    const int tid = threadIdx.x;
    const int ty  = tid >> 5;          // tile row 0..31
    const int tx  = tid & 31;          // tile col 0..31
    const int tx0 = tx & ~3;           // aligned 4-px group base

    // ---- prefetch ent/kl (coalesced) — starts DRAM/L2 latency early ----
    const int pidx = b * HW + (i0 + ty) * WW + j0 + tx;
    const float entv = g_ent[pidx];
    const float klv  = g_kl[pidx];
    const float Hm = __int_as_float(g_entmax[b]);

    __shared__ unsigned char sfg[EW][56];   // fg halo: col cc = global j0-12+cc
    __shared__ unsigned char svv[TS][56];   // vertical min-d^2

    // ---- fg halo: 52 rows x 14 aligned u32 words (single step, tid<728) ----
    if (tid < EW * 14) {
        int r = tid / 14, k = tid - r * 14;
        int gi = i0 - RAD + r;
        int g0 = j0 - 12 + 4 * k;       // j0 % 32 == 0 -> g0 % 4 == 0
        unsigned int word = 0;
        if (gi >= 0 && gi < HH) {
            const unsigned char* rowp = g_fg + b * HW + gi * WW;
            if (g0 >= 0 && g0 + 3 < WW) {
                word = *(const unsigned int*)(rowp + g0);
            } else {
#pragma unroll
                for (int bb = 0; bb < 4; bb++) {
                    int gj = g0 + bb;
                    if (gj >= 0 && gj < WW)
                        word |= (unsigned int)rowp[gj] << (8 * bb);
                }
            }
        }
        *(unsigned int*)&sfg[r][4 * k] = word;
    }
    __syncthreads();

    // ---- vertical 21-tap min, byte SIMD: term = 200 - fg*(200-d^2) ----
    if (tid < TS * 14) {
        int r = tid / 14, wc = (tid - r * 14) * 4;
        unsigned int v4 = 0xC8C8C8C8u;
#pragma unroll
        for (int dr = 0; dr < 21; dr++) {
            unsigned int f4 = *(const unsigned int*)&sfg[r + dr][wc];
            int d = dr - RAD;
            v4 = __vminu4(v4, 0xC8C8C8C8u - f4 * (unsigned int)(200 - d * d));
        }
        *(unsigned int*)&svv[r][wc] = v4;
    }
    __syncthreads();

    // ---- horizontal 21-tap min (byte SIMD over the 4-px group) ----
    unsigned int w[7];
#pragma unroll
    for (int k = 0; k < 7; k++)
        w[k] = *(const unsigned int*)&svv[ty][tx0 + 4 * k];

    unsigned int m4 = 0xC8C8C8C8u;
#pragma unroll
    for (int s = 0; s < 21; s++) {
        const int o = s + 2;
        const unsigned int sel = 0x3210u + 0x1111u * (o & 3);
        unsigned int V = __byte_perm(w[o >> 2], w[(o >> 2) + 1], sel);
        const int dd = s - RAD;
        const unsigned int C = (unsigned int)(dd * dd) * 0x01010101u;
        m4 = __vminu4(m4, __vaddus4(V, C));   // saturation only above threshold
    }

    // ---- weight for this thread's single pixel ----
    float a_wkl = 0.f, a_w = 0.f;
    {
        const int d2 = (m4 >> (8 * (tx & 3))) & 0xFF;
        if (d2 <= RAD * RAD) {
            float wd = __expf((float)d2 * (-1.0f / 50.0f));  // 2*sigma^2 = 50
            float bnd = 0.f;
            if (sfg[ty + RAD][tx + 12]) {
                bool er = sfg[ty + RAD - 1][tx + 12] && sfg[ty + RAD + 1][tx + 12]
                       && sfg[ty + RAD][tx + 11] && sfg[ty + RAD][tx + 13];
                if (!er) bnd = 1.f;
            }
            float conf = 0.1f + 0.9f * (1.f - entv / (Hm + 1e-8f));
            float wgt = wd * (1.f + bnd) * conf;
            a_wkl = wgt * klv;
            a_w   = wgt;
        }
    }

    // ---- reduce (32 warps) + finalize ----
#pragma unroll
    for (int o = 16; o > 0; o >>= 1) {
        a_wkl += __shfl_xor_sync(0xFFFFFFFF, a_wkl, o);
        a_w   += __shfl_xor_sync(0xFFFFFFFF, a_w, o);
    }
    __shared__ float r1[32], r2[32];
    if ((tid & 31) == 0) { r1[tid >> 5] = a_wkl; r2[tid >> 5] = a_w; }
    __syncthreads();

    if (tid < 32) {
        float s1 = r1[tid], s2 = r2[tid];
#pragma unroll
        for (int o = 16; o > 0; o >>= 1) {
            s1 += __shfl_xor_sync(0xFFFFFFFF, s1, o);
            s2 += __shfl_xor_sync(0xFFFFFFFF, s2, o);
        }
        if (tid == 0) {
            atomicAdd(&g_sum_wkl, (double)s1);
            atomicAdd(&g_sum_w, (double)s2);
            __threadfence();
            unsigned int t = atomicAdd(&g_done, 1u);
            if (t == NBLK2 - 1) {   // last block: finalize + reset for next replay
                double swkl = atomicAdd(&g_sum_wkl, 0.0);
                double sw   = atomicAdd(&g_sum_w, 0.0);
                out[0] = (float)(16.0 * swkl / (sw + 1e-8));
                g_sum_wkl = 0.0;
                g_sum_w = 0.0;
#pragma unroll
                for (int bb = 0; bb < BB; bb++) g_entmax[bb] = 0;
                atomicExch(&g_done, 0u);
            }
        }
    }
}

extern "C" void kernel_launch(void* const* d_in, const int* in_sizes, int n_in,
                              void* d_out, int out_size)
{
    const float* student = (const float*)d_in[0];
    const float* teacher = (const float*)d_in[1];
    float* out = (float*)d_out;

    k1_channelwise<<<dim3(HW / 256, BB), 256>>>(student, teacher);
    k2_edt_weights<<<dim3(64, BB), 1024>>>(out);
}

// round 7
// speedup vs baseline: 1.1196x; 1.1196x over previous
#include <cuda_runtime.h>

// Fixed problem shape
#define BB 4
#define CC 19
#define HH 256
#define WW 256
#define HW (HH * WW)
#define CHW (CC * HW)
#define RAD 10
#define TS 32
#define EW (TS + 2 * RAD)   // 52 halo rows
#define NBLK2 256           // K2 block count (64 tiles x 4 images)

// Scratch (device globals; self-resetting at end of each replay)
__device__ float g_ent[BB * HW];
__device__ float g_kl[BB * HW];
__device__ unsigned char g_fg[BB * HW];
__device__ int g_entmax[BB];        // entropy > 0 -> int atomicMax is order-preserving
__device__ double g_sum_wkl;
__device__ double g_sum_w;
__device__ unsigned int g_done;     // K2 completion counter

// ---------------------------------------------------------------------------
// K1: 1 pixel/thread, max occupancy, perfectly coalesced. (at LTS roofline)
// ---------------------------------------------------------------------------
__global__ void __launch_bounds__(256) k1_channelwise(
    const float* __restrict__ student, const float* __restrict__ teacher)
{
    const int b = blockIdx.y;
    const int p = blockIdx.x * 256 + threadIdx.x;
    const size_t base = (size_t)b * CHW + p;

    float Z = 0.f, S = 0.f, Tt = 0.f, Zs = 0.f;
    float t0, mx = -1e30f;

#pragma unroll
    for (int c = 0; c < CC; c++) {
        float tv = __ldg(teacher + base + (size_t)c * HW) * 0.25f;
        float sv = __ldg(student + base + (size_t)c * HW) * 0.25f;
        float e = __expf(tv);
        Z += e;
        S = fmaf(e, tv, S);
        Tt = fmaf(e, sv, Tt);
        Zs += __expf(sv);
        if (c == 0) t0 = tv;
        else        mx = fmaxf(mx, tv);
    }

    const float lZ = __logf(Z);
    const float ent = lZ - S / Z;
    const float kl = (S - Tt) / Z - lZ + __logf(Zs);

    const int idx = b * HW + p;
    g_ent[idx] = ent;
    g_kl[idx] = kl;
    g_fg[idx] = (mx > t0) ? 1 : 0;   // argmax != 0 (ties -> class 0)

    float entm = ent;
#pragma unroll
    for (int o = 16; o > 0; o >>= 1)
        entm = fmaxf(entm, __shfl_xor_sync(0xFFFFFFFF, entm, o));
    __shared__ float smax[8];
    if ((threadIdx.x & 31) == 0) smax[threadIdx.x >> 5] = entm;
    __syncthreads();
    if (threadIdx.x == 0) {
        float m = smax[0];
#pragma unroll
        for (int w = 1; w < 8; w++) m = fmaxf(m, smax[w]);
        atomicMax(&g_entmax[b], __float_as_int(m));
    }
}

// ---------------------------------------------------------------------------
// K2: bounded EDT + weights + finalize.
// 1024 threads/block (55 warps/SM), 1 pixel/thread, NO redundant work:
//  - halo as aligned u32 word loads
//  - vertical 21-tap min: byte-SIMD, 2-way split chains (448 words, 1 step)
//  - horizontal 21-tap min: scalar, 21 INDEPENDENT byte-LDS (conflict-free)
//    + 3-way split min chains -> short critical path, LSU-pipe bound
// ---------------------------------------------------------------------------
__global__ void __launch_bounds__(1024) k2_edt_weights(float* __restrict__ out)
{
    const int b  = blockIdx.y;
    const int i0 = (blockIdx.x >> 3) * TS;
    const int j0 = (blockIdx.x & 7) * TS;
    const int tid = threadIdx.x;
    const int ty  = tid >> 5;          // tile row 0..31
    const int tx  = tid & 31;          // tile col 0..31

    // ---- prefetch ent/kl (coalesced) — starts L2 latency early ----
    const int pidx = b * HW + (i0 + ty) * WW + j0 + tx;
    const float entv = g_ent[pidx];
    const float klv  = g_kl[pidx];
    const float Hm = __int_as_float(g_entmax[b]);

    __shared__ unsigned char sfg[EW][56];   // fg halo: col cc = global j0-12+cc
    __shared__ unsigned char svv[TS][56];   // vertical min-d^2

    // ---- fg halo: 52 rows x 14 aligned u32 words (single step, tid<728) ----
    if (tid < EW * 14) {
        int r = tid / 14, k = tid - r * 14;
        int gi = i0 - RAD + r;
        int g0 = j0 - 12 + 4 * k;       // j0 % 32 == 0 -> g0 % 4 == 0
        unsigned int word = 0;
        if (gi >= 0 && gi < HH) {
            const unsigned char* rowp = g_fg + b * HW + gi * WW;
            if (g0 >= 0 && g0 + 3 < WW) {
                word = *(const unsigned int*)(rowp + g0);
            } else {
#pragma unroll
                for (int bb = 0; bb < 4; bb++) {
                    int gj = g0 + bb;
                    if (gj >= 0 && gj < WW)
                        word |= (unsigned int)rowp[gj] << (8 * bb);
                }
            }
        }
        *(unsigned int*)&sfg[r][4 * k] = word;
    }
    __syncthreads();

    // ---- vertical 21-tap min, byte SIMD, 2 independent chains ----
    if (tid < TS * 14) {
        int r = tid / 14, wc = (tid - r * 14) * 4;
        unsigned int va = 0xC8C8C8C8u, vb = 0xC8C8C8C8u;
#pragma unroll
        for (int dr = 0; dr < 21; dr += 2) {
            unsigned int f4 = *(const unsigned int*)&sfg[r + dr][wc];
            int d = dr - RAD;
            va = __vminu4(va, 0xC8C8C8C8u - f4 * (unsigned int)(200 - d * d));
        }
#pragma unroll
        for (int dr = 1; dr < 21; dr += 2) {
            unsigned int f4 = *(const unsigned int*)&sfg[r + dr][wc];
            int d = dr - RAD;
            vb = __vminu4(vb, 0xC8C8C8C8u - f4 * (unsigned int)(200 - d * d));
        }
        *(unsigned int*)&svv[r][wc] = __vminu4(va, vb);
    }
    __syncthreads();

    // ---- horizontal 21-tap min: scalar taps (independent LDS), 3 chains ----
    // pixel col tx -> smem cc = tx+12; taps cc-10..cc+10 = tx+2 .. tx+22
    int m0 = 300, m1 = 300, m2 = 300;
#pragma unroll
    for (int s = 0; s < 7; s++) {
        int dd = s - RAD;
        m0 = min(m0, dd * dd + (int)svv[ty][tx + 2 + s]);
    }
#pragma unroll
    for (int s = 7; s < 14; s++) {
        int dd = s - RAD;
        m1 = min(m1, dd * dd + (int)svv[ty][tx + 2 + s]);
    }
#pragma unroll
    for (int s = 14; s < 21; s++) {
        int dd = s - RAD;
        m2 = min(m2, dd * dd + (int)svv[ty][tx + 2 + s]);
    }
    const int d2 = min(m0, min(m1, m2));

    // ---- weight for this thread's pixel ----
    float a_wkl = 0.f, a_w = 0.f;
    if (d2 <= RAD * RAD) {
        float wd = __expf((float)d2 * (-1.0f / 50.0f));  // 2*sigma^2 = 50
        float bnd = 0.f;
        if (sfg[ty + RAD][tx + 12]) {
            bool er = sfg[ty + RAD - 1][tx + 12] && sfg[ty + RAD + 1][tx + 12]
                   && sfg[ty + RAD][tx + 11] && sfg[ty + RAD][tx + 13];
            if (!er) bnd = 1.f;
        }
        float conf = 0.1f + 0.9f * (1.f - entv / (Hm + 1e-8f));
        float wgt = wd * (1.f + bnd) * conf;
        a_wkl = wgt * klv;
        a_w   = wgt;
    }

    // ---- reduce (32 warps) + finalize ----
#pragma unroll
    for (int o = 16; o > 0; o >>= 1) {
        a_wkl += __shfl_xor_sync(0xFFFFFFFF, a_wkl, o);
        a_w   += __shfl_xor_sync(0xFFFFFFFF, a_w, o);
    }
    __shared__ float r1[32], r2[32];
    if ((tid & 31) == 0) { r1[tid >> 5] = a_wkl; r2[tid >> 5] = a_w; }
    __syncthreads();

    if (tid < 32) {
        float s1 = r1[tid], s2 = r2[tid];
#pragma unroll
        for (int o = 16; o > 0; o >>= 1) {
            s1 += __shfl_xor_sync(0xFFFFFFFF, s1, o);
            s2 += __shfl_xor_sync(0xFFFFFFFF, s2, o);
        }
        if (tid == 0) {
            atomicAdd(&g_sum_wkl, (double)s1);
            atomicAdd(&g_sum_w, (double)s2);
            __threadfence();
            unsigned int t = atomicAdd(&g_done, 1u);
            if (t == NBLK2 - 1) {   // last block: finalize + reset for next replay
                double swkl = atomicAdd(&g_sum_wkl, 0.0);
                double sw   = atomicAdd(&g_sum_w, 0.0);
                out[0] = (float)(16.0 * swkl / (sw + 1e-8));
                g_sum_wkl = 0.0;
                g_sum_w = 0.0;
#pragma unroll
                for (int bb = 0; bb < BB; bb++) g_entmax[bb] = 0;
                atomicExch(&g_done, 0u);
            }
        }
    }
}

extern "C" void kernel_launch(void* const* d_in, const int* in_sizes, int n_in,
                              void* d_out, int out_size)
{
    const float* student = (const float*)d_in[0];
    const float* teacher = (const float*)d_in[1];
    float* out = (float*)d_out;

    k1_channelwise<<<dim3(HW / 256, BB), 256>>>(student, teacher);
    k2_edt_weights<<<dim3(64, BB), 1024>>>(out);
}